// round 4
// baseline (speedup 1.0000x reference)
#include <cuda_runtime.h>
#include <math.h>

#define Bz   8
#define Sq   1024
#define Dm   1024
#define Hn   16
#define HDim 64
#define Ff   4096
#define NL   6
#define NTOK (Bz*Sq)   /* 8192 tokens */

// One big scratch buffer: X,Q,K,V,T1,T2 (8192x1024 each) + H1 (8192x4096)
__device__ float g_buf[(size_t)NTOK*Dm*6 + (size_t)NTOK*Ff];

// ---------------------------------------------------------------------------
// Embedding * sqrt(D) + sinusoidal PE
// ---------------------------------------------------------------------------
__global__ void embed_kernel(const int* __restrict__ src, const float* __restrict__ emb,
                             float* __restrict__ X)
{
    int row = blockIdx.x;          // b*S + s
    int s   = row % Sq;
    int tok = src[row];
    const float* er = emb + (size_t)tok * Dm;
    float* xr = X + (size_t)row * Dm;
    #pragma unroll
    for (int e = 0; e < 4; e++) {
        int d  = threadIdx.x + e * 256;
        int j2 = (d >> 1) * 2;                       // even index of the pair
        float div = powf(10000.0f, (float)j2 / (float)Dm);
        float ang = (float)s / div;
        float pe  = (d & 1) ? cosf(ang) : sinf(ang);
        xr[d] = er[d] * 32.0f + pe;                  // sqrt(1024) = 32
    }
}

// ---------------------------------------------------------------------------
// C[M,N] = A[M,K] @ B[K,N] + bias[N]  (optional ReLU)
// 128x128x16 tiles, 256 threads, 8x8 micro-tile
// ---------------------------------------------------------------------------
__global__ __launch_bounds__(256)
void gemm_kernel(const float* __restrict__ A, const float* __restrict__ B,
                 const float* __restrict__ bias, float* __restrict__ C,
                 int M, int N, int K, int relu)
{
    __shared__ float As[16][132];   // transposed A tile (k-major), padded
    __shared__ float Bs[16][128];
    int tid = threadIdx.x;
    int tx = tid & 15, ty = tid >> 4;
    int bn = blockIdx.x * 128, bm = blockIdx.y * 128;

    float acc[8][8];
    #pragma unroll
    for (int i = 0; i < 8; i++)
        #pragma unroll
        for (int j = 0; j < 8; j++) acc[i][j] = 0.f;

    for (int k0 = 0; k0 < K; k0 += 16) {
        #pragma unroll
        for (int v = 0; v < 2; v++) {                 // A tile: 128x16
            int idx = tid + v * 256;
            int row = idx >> 2;
            int kc  = (idx & 3) << 2;
            float4 a = *(const float4*)(A + (size_t)(bm + row) * K + k0 + kc);
            As[kc + 0][row] = a.x; As[kc + 1][row] = a.y;
            As[kc + 2][row] = a.z; As[kc + 3][row] = a.w;
        }
        #pragma unroll
        for (int v = 0; v < 2; v++) {                 // B tile: 16x128
            int idx = tid + v * 256;
            int row = idx >> 5;
            int c   = (idx & 31) << 2;
            *(float4*)&Bs[row][c] = *(const float4*)(B + (size_t)(k0 + row) * N + bn + c);
        }
        __syncthreads();
        #pragma unroll
        for (int kk = 0; kk < 16; kk++) {
            float a[8], b[8];
            *(float4*)(a)     = *(float4*)&As[kk][ty * 8];
            *(float4*)(a + 4) = *(float4*)&As[kk][ty * 8 + 4];
            *(float4*)(b)     = *(float4*)&Bs[kk][tx * 8];
            *(float4*)(b + 4) = *(float4*)&Bs[kk][tx * 8 + 4];
            #pragma unroll
            for (int i = 0; i < 8; i++)
                #pragma unroll
                for (int j = 0; j < 8; j++)
                    acc[i][j] = fmaf(a[i], b[j], acc[i][j]);
        }
        __syncthreads();
    }

    #pragma unroll
    for (int i = 0; i < 8; i++) {
        int row = bm + ty * 8 + i;
        #pragma unroll
        for (int j4 = 0; j4 < 2; j4++) {
            int col = bn + tx * 8 + j4 * 4;
            float4 r;
            r.x = acc[i][j4*4+0] + bias[col+0];
            r.y = acc[i][j4*4+1] + bias[col+1];
            r.z = acc[i][j4*4+2] + bias[col+2];
            r.w = acc[i][j4*4+3] + bias[col+3];
            if (relu) {
                r.x = fmaxf(r.x, 0.f); r.y = fmaxf(r.y, 0.f);
                r.z = fmaxf(r.z, 0.f); r.w = fmaxf(r.w, 0.f);
            }
            *(float4*)(C + (size_t)row * N + col) = r;
        }
    }
}

// ---------------------------------------------------------------------------
// Flash-style attention: one block = (b, h, 64-row q tile), online softmax
// ---------------------------------------------------------------------------
#define SSTR 65
__global__ __launch_bounds__(256)
void attn_kernel(const float* __restrict__ Q, const float* __restrict__ Kd,
                 const float* __restrict__ V, const int* __restrict__ mask,
                 float* __restrict__ O)
{
    extern __shared__ float sm[];
    float* Qs = sm;
    float* Ks = Qs + 64 * SSTR;
    float* Vs = Ks + 64 * SSTR;
    float* Ps = Vs + 64 * SSTR;

    int q0 = blockIdx.x * 64;
    int h  = blockIdx.y, b = blockIdx.z;
    int tid = threadIdx.x;
    int tx = tid & 15, ty = tid >> 4;
    size_t baseq = ((size_t)b * Sq + q0) * Dm + h * HDim;

    #pragma unroll
    for (int e = 0; e < 16; e++) {
        int idx = e * 256 + tid;
        int r = idx >> 6, c = idx & 63;
        Qs[r * SSTR + c] = Q[baseq + (size_t)r * Dm + c];
    }

    float mrow[4], lrow[4], acc[4][4];
    #pragma unroll
    for (int i = 0; i < 4; i++) {
        mrow[i] = -1e30f; lrow[i] = 0.f;
        #pragma unroll
        for (int j = 0; j < 4; j++) acc[i][j] = 0.f;
    }
    const int* mrowp = mask + (size_t)b * Sq;

    for (int k0 = 0; k0 < Sq; k0 += 64) {
        __syncthreads();   // protect K/V/P reuse across iterations
        size_t basek = ((size_t)b * Sq + k0) * Dm + h * HDim;
        #pragma unroll
        for (int e = 0; e < 16; e++) {
            int idx = e * 256 + tid;
            int r = idx >> 6, c = idx & 63;
            Ks[r * SSTR + c] = Kd[basek + (size_t)r * Dm + c];
            Vs[r * SSTR + c] = V [basek + (size_t)r * Dm + c];
        }
        __syncthreads();

        float s[4][4];
        #pragma unroll
        for (int i = 0; i < 4; i++)
            #pragma unroll
            for (int j = 0; j < 4; j++) s[i][j] = 0.f;
        #pragma unroll 8
        for (int kk = 0; kk < 64; kk++) {
            float aq[4], bk[4];
            #pragma unroll
            for (int i = 0; i < 4; i++) aq[i] = Qs[(ty*4+i)*SSTR + kk];
            #pragma unroll
            for (int j = 0; j < 4; j++) bk[j] = Ks[(tx*4+j)*SSTR + kk];
            #pragma unroll
            for (int i = 0; i < 4; i++)
                #pragma unroll
                for (int j = 0; j < 4; j++)
                    s[i][j] = fmaf(aq[i], bk[j], s[i][j]);
        }
        // scale + mask
        #pragma unroll
        for (int j = 0; j < 4; j++) {
            int kc = k0 + tx * 4 + j;
            bool msk = (mrowp[kc] == 0);
            #pragma unroll
            for (int i = 0; i < 4; i++)
                s[i][j] = msk ? -1e10f : s[i][j] * 0.125f;
        }
        // online softmax (row stats reduced across the 16 tx lanes)
        #pragma unroll
        for (int i = 0; i < 4; i++) {
            float tm = fmaxf(fmaxf(s[i][0], s[i][1]), fmaxf(s[i][2], s[i][3]));
            #pragma unroll
            for (int off = 8; off >= 1; off >>= 1)
                tm = fmaxf(tm, __shfl_xor_sync(0xffffffffu, tm, off, 16));
            float nm   = fmaxf(mrow[i], tm);
            float corr = __expf(mrow[i] - nm);
            float rs = 0.f;
            #pragma unroll
            for (int j = 0; j < 4; j++) { s[i][j] = __expf(s[i][j] - nm); rs += s[i][j]; }
            #pragma unroll
            for (int off = 8; off >= 1; off >>= 1)
                rs += __shfl_xor_sync(0xffffffffu, rs, off, 16);
            lrow[i] = lrow[i] * corr + rs;
            mrow[i] = nm;
            #pragma unroll
            for (int j = 0; j < 4; j++) acc[i][j] *= corr;
        }
        #pragma unroll
        for (int i = 0; i < 4; i++)
            #pragma unroll
            for (int j = 0; j < 4; j++)
                Ps[(ty*4+i)*SSTR + tx*4+j] = s[i][j];
        __syncthreads();
        #pragma unroll 8
        for (int kk = 0; kk < 64; kk++) {
            float pv[4], vv[4];
            #pragma unroll
            for (int i = 0; i < 4; i++) pv[i] = Ps[(ty*4+i)*SSTR + kk];
            #pragma unroll
            for (int j = 0; j < 4; j++) vv[j] = Vs[kk*SSTR + tx*4+j];
            #pragma unroll
            for (int i = 0; i < 4; i++)
                #pragma unroll
                for (int j = 0; j < 4; j++)
                    acc[i][j] = fmaf(pv[i], vv[j], acc[i][j]);
        }
    }

    #pragma unroll
    for (int i = 0; i < 4; i++) {
        float inv = 1.f / lrow[i];
        float4 r;
        r.x = acc[i][0]*inv; r.y = acc[i][1]*inv;
        r.z = acc[i][2]*inv; r.w = acc[i][3]*inv;
        *(float4*)(O + baseq + (size_t)(ty*4+i) * Dm + tx*4) = r;
    }
}

// ---------------------------------------------------------------------------
// dst = LayerNorm(x + t) * g + b        (one block per token row of 1024)
// ---------------------------------------------------------------------------
__device__ __forceinline__ float block_reduce_sum(float v, float* red)
{
    #pragma unroll
    for (int o = 16; o > 0; o >>= 1) v += __shfl_xor_sync(0xffffffffu, v, o);
    int w = threadIdx.x >> 5;
    if ((threadIdx.x & 31) == 0) red[w] = v;
    __syncthreads();
    if (threadIdx.x < 32) {
        float r = (threadIdx.x < 8) ? red[threadIdx.x] : 0.f;
        #pragma unroll
        for (int o = 4; o > 0; o >>= 1) r += __shfl_xor_sync(0xffffffffu, r, o);
        if (threadIdx.x == 0) red[0] = r;
    }
    __syncthreads();
    float r = red[0];
    __syncthreads();
    return r;
}

__global__ __launch_bounds__(256)
void add_ln_kernel(const float* __restrict__ x, const float* __restrict__ t,
                   const float* __restrict__ g, const float* __restrict__ bt,
                   float* __restrict__ dst)
{
    __shared__ float red[8];
    size_t base = (size_t)blockIdx.x * Dm;
    float v[4]; float s = 0.f;
    #pragma unroll
    for (int e = 0; e < 4; e++) {
        int c = threadIdx.x + e * 256;
        v[e] = x[base + c] + t[base + c];
        s += v[e];
    }
    s = block_reduce_sum(s, red);
    float mu = s * (1.0f / Dm);
    float q = 0.f;
    #pragma unroll
    for (int e = 0; e < 4; e++) { float d = v[e] - mu; q += d * d; }
    q = block_reduce_sum(q, red);
    float inv = rsqrtf(q * (1.0f / Dm) + 1e-5f);
    #pragma unroll
    for (int e = 0; e < 4; e++) {
        int c = threadIdx.x + e * 256;
        dst[base + c] = (v[e] - mu) * inv * g[c] + bt[c];
    }
}

// ---------------------------------------------------------------------------
extern "C" void kernel_launch(void* const* d_in, const int* in_sizes, int n_in,
                              void* d_out, int out_size)
{
    const int*   src = (const int*)d_in[0];
    const int*   msk = (const int*)d_in[1];
    const float* emb = (const float*)d_in[2];
    const float* Wq  = (const float*)d_in[3];
    const float* bq  = (const float*)d_in[4];
    const float* Wk  = (const float*)d_in[5];
    const float* bk  = (const float*)d_in[6];
    const float* Wv  = (const float*)d_in[7];
    const float* bv  = (const float*)d_in[8];
    const float* Wo  = (const float*)d_in[9];
    const float* bo  = (const float*)d_in[10];
    const float* g1  = (const float*)d_in[11];
    const float* b1n = (const float*)d_in[12];
    const float* W1  = (const float*)d_in[13];
    const float* b1  = (const float*)d_in[14];
    const float* W2  = (const float*)d_in[15];
    const float* b2  = (const float*)d_in[16];
    const float* g2  = (const float*)d_in[17];
    const float* b2n = (const float*)d_in[18];
    float* out = (float*)d_out;

    float* base = nullptr;
    cudaGetSymbolAddress((void**)&base, g_buf);
    float* X  = base;
    float* Qb = base + (size_t)NTOK * Dm;
    float* Kb = base + (size_t)NTOK * Dm * 2;
    float* Vb = base + (size_t)NTOK * Dm * 3;
    float* T1 = base + (size_t)NTOK * Dm * 4;
    float* T2 = base + (size_t)NTOK * Dm * 5;
    float* H1 = base + (size_t)NTOK * Dm * 6;

    const int ATTN_SMEM = 4 * 64 * SSTR * 4;   // 66560 bytes
    cudaFuncSetAttribute((const void*)attn_kernel,
                         cudaFuncAttributeMaxDynamicSharedMemorySize, ATTN_SMEM);

    embed_kernel<<<NTOK, 256>>>(src, emb, X);

    dim3 gD(Dm / 128, NTOK / 128);   // (8, 64)
    dim3 gF(Ff / 128, NTOK / 128);   // (32, 64)
    dim3 gA(Sq / 64, Hn, Bz);        // (16, 16, 8)

    for (int l = 0; l < NL; l++) {
        size_t oDD = (size_t)l * Dm * Dm;
        size_t oD  = (size_t)l * Dm;
        size_t oDF = (size_t)l * Dm * Ff;
        size_t oF  = (size_t)l * Ff;

        gemm_kernel<<<gD, 256>>>(X,  Wq + oDD, bq + oD, Qb, NTOK, Dm, Dm, 0);
        gemm_kernel<<<gD, 256>>>(X,  Wk + oDD, bk + oD, Kb, NTOK, Dm, Dm, 0);
        gemm_kernel<<<gD, 256>>>(X,  Wv + oDD, bv + oD, Vb, NTOK, Dm, Dm, 0);
        attn_kernel<<<gA, 256, ATTN_SMEM>>>(Qb, Kb, Vb, msk, T1);
        gemm_kernel<<<gD, 256>>>(T1, Wo + oDD, bo + oD, T2, NTOK, Dm, Dm, 0);
        add_ln_kernel<<<NTOK, 256>>>(X, T2, g1 + oD, b1n + oD, X);
        gemm_kernel<<<gF, 256>>>(X,  W1 + oDF, b1 + oF, H1, NTOK, Ff, Dm, 1);
        gemm_kernel<<<gD, 256>>>(H1, W2 + oDF, b2 + oD, T2, NTOK, Dm, Ff, 0);
        add_ln_kernel<<<NTOK, 256>>>(X, T2, g2 + oD, b2n + oD, (l == NL - 1) ? out : X);
    }
}

// round 7
// speedup vs baseline: 2.1415x; 2.1415x over previous
#include <cuda_runtime.h>
#include <cuda_bf16.h>
#include <math.h>
#include <stdint.h>

#define Bz   8
#define Sq   1024
#define Dm   1024
#define Hn   16
#define HDim 64
#define Ff   4096
#define NL   6
#define NTOK (Bz*Sq)   /* 8192 tokens */

// fp32 scratch: X,Q,K,V,T1,T2 (8192x1024 each) + H1 (8192x4096)
__device__ float g_buf[(size_t)NTOK*Dm*6 + (size_t)NTOK*Ff];
// bf16 hi/lo activation scratch (sized for H1 = 8192x4096)
__device__ __nv_bfloat16 g_act_hi[(size_t)NTOK*Ff];
__device__ __nv_bfloat16 g_act_lo[(size_t)NTOK*Ff];
// bf16 hi/lo transposed weights: per layer 12M elems (Wq,Wk,Wv,Wo 1M each; W1t,W2t 4M each)
__device__ __nv_bfloat16 g_wt_hi[(size_t)NL*12*1024*1024];
__device__ __nv_bfloat16 g_wt_lo[(size_t)NL*12*1024*1024];

// ---------------------------------------------------------------------------
// helpers
// ---------------------------------------------------------------------------
__device__ __forceinline__ uint32_t smem_u32(const void* p) {
    uint32_t a;
    asm("{ .reg .u64 t; cvta.to.shared.u64 t, %1; cvt.u32.u64 %0, t; }" : "=r"(a) : "l"(p));
    return a;
}

__device__ __forceinline__ void ldsm4(uint32_t* r, uint32_t addr) {
    asm volatile("ldmatrix.sync.aligned.m8n8.x4.shared.b16 {%0,%1,%2,%3}, [%4];"
        : "=r"(r[0]), "=r"(r[1]), "=r"(r[2]), "=r"(r[3]) : "r"(addr));
}

__device__ __forceinline__ void mma16816(float* c, const uint32_t* a, const uint32_t* b) {
    asm volatile(
        "mma.sync.aligned.m16n8k16.row.col.f32.bf16.bf16.f32 "
        "{%0,%1,%2,%3}, {%4,%5,%6,%7}, {%8,%9}, {%0,%1,%2,%3};"
        : "+f"(c[0]), "+f"(c[1]), "+f"(c[2]), "+f"(c[3])
        : "r"(a[0]), "r"(a[1]), "r"(a[2]), "r"(a[3]), "r"(b[0]), "r"(b[1]));
}

// ---------------------------------------------------------------------------
// Embedding * sqrt(D) + sinusoidal PE
// ---------------------------------------------------------------------------
__global__ void embed_kernel(const int* __restrict__ src, const float* __restrict__ emb,
                             float* __restrict__ X)
{
    int row = blockIdx.x;
    int s   = row % Sq;
    int tok = src[row];
    const float* er = emb + (size_t)tok * Dm;
    float* xr = X + (size_t)row * Dm;
    #pragma unroll
    for (int e = 0; e < 4; e++) {
        int d  = threadIdx.x + e * 256;
        int j2 = (d >> 1) * 2;
        float div = powf(10000.0f, (float)j2 / (float)Dm);
        float ang = (float)s / div;
        float pe  = (d & 1) ? cosf(ang) : sinf(ang);
        xr[d] = er[d] * 32.0f + pe;
    }
}

// ---------------------------------------------------------------------------
// fp32 -> (hi, lo) bf16 split, elementwise
// ---------------------------------------------------------------------------
__global__ __launch_bounds__(256)
void act_conv_kernel(const float* __restrict__ x, __nv_bfloat16* __restrict__ hi,
                     __nv_bfloat16* __restrict__ lo, int n4)
{
    int i = blockIdx.x * 256 + threadIdx.x;
    if (i >= n4) return;
    float4 v = ((const float4*)x)[i];
    __nv_bfloat16 h0 = __float2bfloat16(v.x), h1 = __float2bfloat16(v.y);
    __nv_bfloat16 h2 = __float2bfloat16(v.z), h3 = __float2bfloat16(v.w);
    __nv_bfloat16 l0 = __float2bfloat16(v.x - __bfloat162float(h0));
    __nv_bfloat16 l1 = __float2bfloat16(v.y - __bfloat162float(h1));
    __nv_bfloat16 l2 = __float2bfloat16(v.z - __bfloat162float(h2));
    __nv_bfloat16 l3 = __float2bfloat16(v.w - __bfloat162float(h3));
    ((__nv_bfloat162*)hi)[i*2]   = __nv_bfloat162(h0, h1);
    ((__nv_bfloat162*)hi)[i*2+1] = __nv_bfloat162(h2, h3);
    ((__nv_bfloat162*)lo)[i*2]   = __nv_bfloat162(l0, l1);
    ((__nv_bfloat162*)lo)[i*2+1] = __nv_bfloat162(l2, l3);
}

// ---------------------------------------------------------------------------
// Weight transpose + hi/lo split: W[K,N] fp32 -> Wt_hi/Wt_lo[N,K] bf16
// ---------------------------------------------------------------------------
__global__ __launch_bounds__(256)
void wt_conv_kernel(const float* __restrict__ W, __nv_bfloat16* __restrict__ Thi,
                    __nv_bfloat16* __restrict__ Tlo, int K, int N)
{
    __shared__ float t[32][33];
    int n0 = blockIdx.x * 32, k0 = blockIdx.y * 32;
    int tx = threadIdx.x & 31, ty = threadIdx.x >> 5;    // 32x8
    #pragma unroll
    for (int j = 0; j < 4; j++)
        t[ty + j*8][tx] = W[(size_t)(k0 + ty + j*8) * N + n0 + tx];
    __syncthreads();
    #pragma unroll
    for (int j = 0; j < 4; j++) {
        float v = t[tx][ty + j*8];
        __nv_bfloat16 h = __float2bfloat16(v);
        __nv_bfloat16 l = __float2bfloat16(v - __bfloat162float(h));
        size_t idx = (size_t)(n0 + ty + j*8) * K + k0 + tx;
        Thi[idx] = h; Tlo[idx] = l;
    }
}

// ---------------------------------------------------------------------------
// HMMA bf16-split GEMM: C[M,N] = A @ W + bias (+ReLU)
//   A: Ahi/Alo [M,K] bf16 K-major.  B: Bhi/Blo [N,K] bf16 K-major.
//   128x128 CTA tile, BK=64, SW128-swizzled SMEM, 3-stage cp.async pipeline,
//   8 warps (2Mx4N), warp tile 64x32, mma.sync.m16n8k16 (3-term hi/lo split).
// ---------------------------------------------------------------------------
#define TILEB  16384               /* 128 rows x 128B */
#define STAGEB (4*TILEB)           /* Ahi, Alo, Bhi, Blo */
#define NSTAGE 3
#define GEMM_SMEM (NSTAGE*STAGEB)  /* 196608 */

__device__ __forceinline__ void load_stage(
    uint32_t stage_base, const __nv_bfloat16* Ahi, const __nv_bfloat16* Alo,
    const __nv_bfloat16* Bhi, const __nv_bfloat16* Blo,
    int bm, int bn, int K, int k0, int tid)
{
    const __nv_bfloat16* srcs[4] = {Ahi, Alo, Bhi, Blo};
    #pragma unroll
    for (int tI = 0; tI < 4; tI++) {
        int rbase = (tI < 2) ? bm : bn;
        const __nv_bfloat16* src = srcs[tI];
        uint32_t tile = stage_base + tI * TILEB;
        #pragma unroll
        for (int i = 0; i < 4; i++) {
            int c   = tid + i * 256;           // 1024 16B chunks per tile
            int row = c >> 3, cb = c & 7;
            uint32_t dst = tile + row * 128 + ((cb ^ (row & 7)) << 4);
            const void* gp = src + ((size_t)(rbase + row) * K + k0 + cb * 8);
            asm volatile("cp.async.cg.shared.global [%0], [%1], 16;" :: "r"(dst), "l"(gp));
        }
    }
    asm volatile("cp.async.commit_group;" ::: "memory");
}

__global__ __launch_bounds__(256, 1)
void gemm_tc_kernel(const __nv_bfloat16* __restrict__ Ahi, const __nv_bfloat16* __restrict__ Alo,
                    const __nv_bfloat16* __restrict__ Bhi, const __nv_bfloat16* __restrict__ Blo,
                    const float* __restrict__ bias, float* __restrict__ C,
                    int M, int N, int K, int relu)
{
    extern __shared__ __align__(1024) char smem[];
    uint32_t sb  = smem_u32(smem);
    int tid = threadIdx.x, wid = tid >> 5, lane = tid & 31;
    int bn = blockIdx.x * 128, bm = blockIdx.y * 128;
    int KSTEPS = K >> 6;

    int r0 = (wid & 1) * 64;     // warp M base within tile
    int n0 = (wid >> 1) * 32;    // warp N base within tile

    float acc[4][4][4];
    #pragma unroll
    for (int a = 0; a < 4; a++)
        #pragma unroll
        for (int b = 0; b < 4; b++)
            #pragma unroll
            for (int c = 0; c < 4; c++) acc[a][b][c] = 0.f;

    // prologue: fill 2 stages
    load_stage(sb,          Ahi, Alo, Bhi, Blo, bm, bn, K, 0,  tid);
    load_stage(sb + STAGEB, Ahi, Alo, Bhi, Blo, bm, bn, K, 64, tid);

    // per-lane ldmatrix row patterns
    int a_ri = ((lane >> 3) & 1) * 8 + (lane & 7);    // A: row offset within 16-row frag
    int a_ci = (lane >> 4);                           // A: +chunk
    int b_ri = ((lane >> 4) << 3) + (lane & 7);       // B: n offset within 16
    int b_ci = ((lane >> 3) & 1);                     // B: +chunk

    for (int it = 0; it < KSTEPS; it++) {
        if (it == KSTEPS - 1) asm volatile("cp.async.wait_group 0;" ::: "memory");
        else                  asm volatile("cp.async.wait_group 1;" ::: "memory");
        __syncthreads();

        int nx = it + 2;
        if (nx < KSTEPS)
            load_stage(sb + (nx % NSTAGE) * STAGEB, Ahi, Alo, Bhi, Blo,
                       bm, bn, K, nx * 64, tid);

        uint32_t st  = sb + (it % NSTAGE) * STAGEB;
        uint32_t aHb = st, aLb = st + TILEB, bHb = st + 2*TILEB, bLb = st + 3*TILEB;

        #pragma unroll
        for (int ks = 0; ks < 4; ks++) {
            uint32_t aH[4][4], aL[4][4], bH[4][2], bL[4][2];
            int achk = 2 * ks + a_ci;
            #pragma unroll
            for (int mf = 0; mf < 4; mf++) {
                int row = r0 + mf * 16 + a_ri;
                uint32_t off = row * 128 + ((achk ^ (row & 7)) << 4);
                ldsm4(aH[mf], aHb + off);
                ldsm4(aL[mf], aLb + off);
            }
            int bchk = 2 * ks + b_ci;
            #pragma unroll
            for (int g = 0; g < 2; g++) {
                int row = n0 + g * 16 + b_ri;
                uint32_t off = row * 128 + ((bchk ^ (row & 7)) << 4);
                uint32_t t[4];
                ldsm4(t, bHb + off);
                bH[2*g][0] = t[0]; bH[2*g][1] = t[1];
                bH[2*g+1][0] = t[2]; bH[2*g+1][1] = t[3];
                ldsm4(t, bLb + off);
                bL[2*g][0] = t[0]; bL[2*g][1] = t[1];
                bL[2*g+1][0] = t[2]; bL[2*g+1][1] = t[3];
            }
            #pragma unroll
            for (int mf = 0; mf < 4; mf++)
                #pragma unroll
                for (int nf = 0; nf < 4; nf++) {
                    mma16816(acc[mf][nf], aH[mf], bH[nf]);
                    mma16816(acc[mf][nf], aL[mf], bH[nf]);
                    mma16816(acc[mf][nf], aH[mf], bL[nf]);
                }
        }
    }

    // epilogue: bias (+relu), direct register->gmem
    int lrow = lane >> 2, lcol = (lane & 3) * 2;
    #pragma unroll
    for (int mf = 0; mf < 4; mf++) {
        int row = bm + r0 + mf * 16 + lrow;
        #pragma unroll
        for (int nf = 0; nf < 4; nf++) {
            int col = bn + n0 + nf * 8 + lcol;
            float b0 = bias[col], b1 = bias[col + 1];
            float2 v0, v1;
            v0.x = acc[mf][nf][0] + b0; v0.y = acc[mf][nf][1] + b1;
            v1.x = acc[mf][nf][2] + b0; v1.y = acc[mf][nf][3] + b1;
            if (relu) {
                v0.x = fmaxf(v0.x, 0.f); v0.y = fmaxf(v0.y, 0.f);
                v1.x = fmaxf(v1.x, 0.f); v1.y = fmaxf(v1.y, 0.f);
            }
            *(float2*)(C + (size_t)row * N + col)       = v0;
            *(float2*)(C + (size_t)(row + 8) * N + col) = v1;
        }
    }
}

// ---------------------------------------------------------------------------
// Flash-style attention (fp32)
// ---------------------------------------------------------------------------
#define SSTR 65
__global__ __launch_bounds__(256)
void attn_kernel(const float* __restrict__ Q, const float* __restrict__ Kd,
                 const float* __restrict__ V, const int* __restrict__ mask,
                 float* __restrict__ O)
{
    extern __shared__ float sm[];
    float* Qs = sm;
    float* Ks = Qs + 64 * SSTR;
    float* Vs = Ks + 64 * SSTR;
    float* Ps = Vs + 64 * SSTR;

    int q0 = blockIdx.x * 64;
    int h  = blockIdx.y, b = blockIdx.z;
    int tid = threadIdx.x;
    int tx = tid & 15, ty = tid >> 4;
    size_t baseq = ((size_t)b * Sq + q0) * Dm + h * HDim;

    #pragma unroll
    for (int e = 0; e < 16; e++) {
        int idx = e * 256 + tid;
        int r = idx >> 6, c = idx & 63;
        Qs[r * SSTR + c] = Q[baseq + (size_t)r * Dm + c];
    }

    float mrow[4], lrow[4], acc[4][4];
    #pragma unroll
    for (int i = 0; i < 4; i++) {
        mrow[i] = -1e30f; lrow[i] = 0.f;
        #pragma unroll
        for (int j = 0; j < 4; j++) acc[i][j] = 0.f;
    }
    const int* mrowp = mask + (size_t)b * Sq;

    for (int k0 = 0; k0 < Sq; k0 += 64) {
        __syncthreads();
        size_t basek = ((size_t)b * Sq + k0) * Dm + h * HDim;
        #pragma unroll
        for (int e = 0; e < 16; e++) {
            int idx = e * 256 + tid;
            int r = idx >> 6, c = idx & 63;
            Ks[r * SSTR + c] = Kd[basek + (size_t)r * Dm + c];
            Vs[r * SSTR + c] = V [basek + (size_t)r * Dm + c];
        }
        __syncthreads();

        float s[4][4];
        #pragma unroll
        for (int i = 0; i < 4; i++)
            #pragma unroll
            for (int j = 0; j < 4; j++) s[i][j] = 0.f;
        #pragma unroll 8
        for (int kk = 0; kk < 64; kk++) {
            float aq[4], bk[4];
            #pragma unroll
            for (int i = 0; i < 4; i++) aq[i] = Qs[(ty*4+i)*SSTR + kk];
            #pragma unroll
            for (int j = 0; j < 4; j++) bk[j] = Ks[(tx*4+j)*SSTR + kk];
            #pragma unroll
            for (int i = 0; i < 4; i++)
                #pragma unroll
                for (int j = 0; j < 4; j++)
                    s[i][j] = fmaf(aq[i], bk[j], s[i][j]);
        }
        #pragma unroll
        for (int j = 0; j < 4; j++) {
            int kc = k0 + tx * 4 + j;
            bool msk = (mrowp[kc] == 0);
            #pragma unroll
            for (int i = 0; i < 4; i++)
                s[i][j] = msk ? -1e10f : s[i][j] * 0.125f;
        }
        #pragma unroll
        for (int i = 0; i < 4; i++) {
            float tm = fmaxf(fmaxf(s[i][0], s[i][1]), fmaxf(s[i][2], s[i][3]));
            #pragma unroll
            for (int off = 8; off >= 1; off >>= 1)
                tm = fmaxf(tm, __shfl_xor_sync(0xffffffffu, tm, off, 16));
            float nm   = fmaxf(mrow[i], tm);
            float corr = __expf(mrow[i] - nm);
            float rs = 0.f;
            #pragma unroll
            for (int j = 0; j < 4; j++) { s[i][j] = __expf(s[i][j] - nm); rs += s[i][j]; }
            #pragma unroll
            for (int off = 8; off >= 1; off >>= 1)
                rs += __shfl_xor_sync(0xffffffffu, rs, off, 16);
            lrow[i] = lrow[i] * corr + rs;
            mrow[i] = nm;
            #pragma unroll
            for (int j = 0; j < 4; j++) acc[i][j] *= corr;
        }
        #pragma unroll
        for (int i = 0; i < 4; i++)
            #pragma unroll
            for (int j = 0; j < 4; j++)
                Ps[(ty*4+i)*SSTR + tx*4+j] = s[i][j];
        __syncthreads();
        #pragma unroll 8
        for (int kk = 0; kk < 64; kk++) {
            float pv[4], vv[4];
            #pragma unroll
            for (int i = 0; i < 4; i++) pv[i] = Ps[(ty*4+i)*SSTR + kk];
            #pragma unroll
            for (int j = 0; j < 4; j++) vv[j] = Vs[kk*SSTR + tx*4+j];
            #pragma unroll
            for (int i = 0; i < 4; i++)
                #pragma unroll
                for (int j = 0; j < 4; j++)
                    acc[i][j] = fmaf(pv[i], vv[j], acc[i][j]);
        }
    }

    #pragma unroll
    for (int i = 0; i < 4; i++) {
        float inv = 1.f / lrow[i];
        float4 r;
        r.x = acc[i][0]*inv; r.y = acc[i][1]*inv;
        r.z = acc[i][2]*inv; r.w = acc[i][3]*inv;
        *(float4*)(O + baseq + (size_t)(ty*4+i) * Dm + tx*4) = r;
    }
}

// ---------------------------------------------------------------------------
// dst = LayerNorm(x + t) * g + b
// ---------------------------------------------------------------------------
__device__ __forceinline__ float block_reduce_sum(float v, float* red)
{
    #pragma unroll
    for (int o = 16; o > 0; o >>= 1) v += __shfl_xor_sync(0xffffffffu, v, o);
    int w = threadIdx.x >> 5;
    if ((threadIdx.x & 31) == 0) red[w] = v;
    __syncthreads();
    if (threadIdx.x < 32) {
        float r = (threadIdx.x < 8) ? red[threadIdx.x] : 0.f;
        #pragma unroll
        for (int o = 4; o > 0; o >>= 1) r += __shfl_xor_sync(0xffffffffu, r, o);
        if (threadIdx.x == 0) red[0] = r;
    }
    __syncthreads();
    float r = red[0];
    __syncthreads();
    return r;
}

__global__ __launch_bounds__(256)
void add_ln_kernel(const float* __restrict__ x, const float* __restrict__ t,
                   const float* __restrict__ g, const float* __restrict__ bt,
                   float* __restrict__ dst)
{
    __shared__ float red[8];
    size_t base = (size_t)blockIdx.x * Dm;
    float v[4]; float s = 0.f;
    #pragma unroll
    for (int e = 0; e < 4; e++) {
        int c = threadIdx.x + e * 256;
        v[e] = x[base + c] + t[base + c];
        s += v[e];
    }
    s = block_reduce_sum(s, red);
    float mu = s * (1.0f / Dm);
    float q = 0.f;
    #pragma unroll
    for (int e = 0; e < 4; e++) { float d = v[e] - mu; q += d * d; }
    q = block_reduce_sum(q, red);
    float inv = rsqrtf(q * (1.0f / Dm) + 1e-5f);
    #pragma unroll
    for (int e = 0; e < 4; e++) {
        int c = threadIdx.x + e * 256;
        dst[base + c] = (v[e] - mu) * inv * g[c] + bt[c];
    }
}

// ---------------------------------------------------------------------------
extern "C" void kernel_launch(void* const* d_in, const int* in_sizes, int n_in,
                              void* d_out, int out_size)
{
    const int*   src = (const int*)d_in[0];
    const int*   msk = (const int*)d_in[1];
    const float* emb = (const float*)d_in[2];
    const float* Wq  = (const float*)d_in[3];
    const float* bq  = (const float*)d_in[4];
    const float* Wk  = (const float*)d_in[5];
    const float* bk  = (const float*)d_in[6];
    const float* Wv  = (const float*)d_in[7];
    const float* bv  = (const float*)d_in[8];
    const float* Wo  = (const float*)d_in[9];
    const float* bo  = (const float*)d_in[10];
    const float* g1  = (const float*)d_in[11];
    const float* b1n = (const float*)d_in[12];
    const float* W1  = (const float*)d_in[13];
    const float* b1  = (const float*)d_in[14];
    const float* W2  = (const float*)d_in[15];
    const float* b2  = (const float*)d_in[16];
    const float* g2  = (const float*)d_in[17];
    const float* b2n = (const float*)d_in[18];
    float* out = (float*)d_out;

    float* base = nullptr;
    cudaGetSymbolAddress((void**)&base, g_buf);
    float* X  = base;
    float* Qb = base + (size_t)NTOK * Dm;
    float* Kb = base + (size_t)NTOK * Dm * 2;
    float* Vb = base + (size_t)NTOK * Dm * 3;
    float* T1 = base + (size_t)NTOK * Dm * 4;
    float* T2 = base + (size_t)NTOK * Dm * 5;
    float* H1 = base + (size_t)NTOK * Dm * 6;

    __nv_bfloat16 *Ah = nullptr, *Al = nullptr, *Wh = nullptr, *Wl = nullptr;
    cudaGetSymbolAddress((void**)&Ah, g_act_hi);
    cudaGetSymbolAddress((void**)&Al, g_act_lo);
    cudaGetSymbolAddress((void**)&Wh, g_wt_hi);
    cudaGetSymbolAddress((void**)&Wl, g_wt_lo);

    const int ATTN_SMEM = 4 * 64 * SSTR * 4;
    cudaFuncSetAttribute((const void*)attn_kernel,
                         cudaFuncAttributeMaxDynamicSharedMemorySize, ATTN_SMEM);
    cudaFuncSetAttribute((const void*)gemm_tc_kernel,
                         cudaFuncAttributeMaxDynamicSharedMemorySize, GEMM_SMEM);

    const size_t M1 = (size_t)1024 * 1024;
    const size_t LWT = 12 * M1;   // per-layer weight scratch stride

    // Pre-transpose + split all weights (once per launch)
    for (int l = 0; l < NL; l++) {
        size_t oDD = (size_t)l * Dm * Dm, oDF = (size_t)l * Dm * Ff;
        size_t wb = (size_t)l * LWT;
        dim3 tb(256);
        wt_conv_kernel<<<dim3(Dm/32, Dm/32), tb>>>(Wq + oDD, Wh + wb,        Wl + wb,        Dm, Dm);
        wt_conv_kernel<<<dim3(Dm/32, Dm/32), tb>>>(Wk + oDD, Wh + wb + M1,   Wl + wb + M1,   Dm, Dm);
        wt_conv_kernel<<<dim3(Dm/32, Dm/32), tb>>>(Wv + oDD, Wh + wb + 2*M1, Wl + wb + 2*M1, Dm, Dm);
        wt_conv_kernel<<<dim3(Dm/32, Dm/32), tb>>>(Wo + oDD, Wh + wb + 3*M1, Wl + wb + 3*M1, Dm, Dm);
        wt_conv_kernel<<<dim3(Ff/32, Dm/32), tb>>>(W1 + oDF, Wh + wb + 4*M1, Wl + wb + 4*M1, Dm, Ff);
        wt_conv_kernel<<<dim3(Dm/32, Ff/32), tb>>>(W2 + oDF, Wh + wb + 8*M1, Wl + wb + 8*M1, Ff, Dm);
    }

    embed_kernel<<<NTOK, 256>>>(src, emb, X);

    dim3 gD(Dm / 128, NTOK / 128);   // (8, 64)
    dim3 gF(Ff / 128, NTOK / 128);   // (32, 64)
    dim3 gA(Sq / 64, Hn, Bz);
    const int nD4 = NTOK * Dm / 4;
    const int nF4 = NTOK * Ff / 4;

    for (int l = 0; l < NL; l++) {
        size_t oD = (size_t)l * Dm, oF = (size_t)l * Ff;
        size_t wb = (size_t)l * LWT;

        act_conv_kernel<<<nD4/256, 256>>>(X, Ah, Al, nD4);
        gemm_tc_kernel<<<gD, 256, GEMM_SMEM>>>(Ah, Al, Wh + wb,        Wl + wb,        bq + oD, Qb, NTOK, Dm, Dm, 0);
        gemm_tc_kernel<<<gD, 256, GEMM_SMEM>>>(Ah, Al, Wh + wb + M1,   Wl + wb + M1,   bk + oD, Kb, NTOK, Dm, Dm, 0);
        gemm_tc_kernel<<<gD, 256, GEMM_SMEM>>>(Ah, Al, Wh + wb + 2*M1, Wl + wb + 2*M1, bv + oD, Vb, NTOK, Dm, Dm, 0);
        attn_kernel<<<gA, 256, ATTN_SMEM>>>(Qb, Kb, Vb, msk, T1);
        act_conv_kernel<<<nD4/256, 256>>>(T1, Ah, Al, nD4);
        gemm_tc_kernel<<<gD, 256, GEMM_SMEM>>>(Ah, Al, Wh + wb + 3*M1, Wl + wb + 3*M1, bo + oD, T2, NTOK, Dm, Dm, 0);
        add_ln_kernel<<<NTOK, 256>>>(X, T2, g1 + oD, b1n + oD, X);
        act_conv_kernel<<<nD4/256, 256>>>(X, Ah, Al, nD4);
        gemm_tc_kernel<<<gF, 256, GEMM_SMEM>>>(Ah, Al, Wh + wb + 4*M1, Wl + wb + 4*M1, b1 + oF, H1, NTOK, Ff, Dm, 1);
        act_conv_kernel<<<nF4/256, 256>>>(H1, Ah, Al, nF4);
        gemm_tc_kernel<<<gD, 256, GEMM_SMEM>>>(Ah, Al, Wh + wb + 8*M1, Wl + wb + 8*M1, b2 + oD, T2, NTOK, Dm, Ff, 0);
        add_ln_kernel<<<NTOK, 256>>>(X, T2, g2 + oD, b2n + oD, (l == NL - 1) ? out : X);
    }
}

// round 10
// speedup vs baseline: 3.1272x; 1.4603x over previous
#include <cuda_runtime.h>
#include <cuda_bf16.h>
#include <math.h>
#include <stdint.h>

#define Bz   8
#define Sq   1024
#define Dm   1024
#define Hn   16
#define HDim 64
#define Ff   4096
#define NL   6
#define NTOK (Bz*Sq)   /* 8192 tokens */

// fp32 scratch: X, T2
__device__ float g_f32[(size_t)NTOK*Dm*2];
// bf16 hi/lo activation buffers
__device__ __nv_bfloat16 g_xh[(size_t)NTOK*Dm],    g_xl[(size_t)NTOK*Dm];
__device__ __nv_bfloat16 g_qkvh[(size_t)NTOK*3*Dm], g_qkvl[(size_t)NTOK*3*Dm];
__device__ __nv_bfloat16 g_oh[(size_t)NTOK*Dm],    g_ol[(size_t)NTOK*Dm];
__device__ __nv_bfloat16 g_hh[(size_t)NTOK*Ff],    g_hl[(size_t)NTOK*Ff];
// bf16 hi/lo transposed weights: per layer 12M elems (Wqkv 3M, Wo 1M, W1t 4M, W2t 4M)
__device__ __nv_bfloat16 g_wt_hi[(size_t)NL*12*1024*1024];
__device__ __nv_bfloat16 g_wt_lo[(size_t)NL*12*1024*1024];
// packed QKV bias
__device__ float g_bqkv[(size_t)NL*3*Dm];

// ---------------------------------------------------------------------------
// helpers
// ---------------------------------------------------------------------------
__device__ __forceinline__ uint32_t smem_u32(const void* p) {
    uint32_t a;
    asm("{ .reg .u64 t; cvta.to.shared.u64 t, %1; cvt.u32.u64 %0, t; }" : "=r"(a) : "l"(p));
    return a;
}
__device__ __forceinline__ void ldsm4(uint32_t* r, uint32_t addr) {
    asm volatile("ldmatrix.sync.aligned.m8n8.x4.shared.b16 {%0,%1,%2,%3}, [%4];"
        : "=r"(r[0]), "=r"(r[1]), "=r"(r[2]), "=r"(r[3]) : "r"(addr));
}
__device__ __forceinline__ void ldsm4t(uint32_t* r, uint32_t addr) {
    asm volatile("ldmatrix.sync.aligned.m8n8.x4.trans.shared.b16 {%0,%1,%2,%3}, [%4];"
        : "=r"(r[0]), "=r"(r[1]), "=r"(r[2]), "=r"(r[3]) : "r"(addr));
}
__device__ __forceinline__ void mma16816(float* c, const uint32_t* a, const uint32_t* b) {
    asm volatile(
        "mma.sync.aligned.m16n8k16.row.col.f32.bf16.bf16.f32 "
        "{%0,%1,%2,%3}, {%4,%5,%6,%7}, {%8,%9}, {%0,%1,%2,%3};"
        : "+f"(c[0]), "+f"(c[1]), "+f"(c[2]), "+f"(c[3])
        : "r"(a[0]), "r"(a[1]), "r"(a[2]), "r"(a[3]), "r"(b[0]), "r"(b[1]));
}
// two fp32 -> packed bf16x2 hi + bf16x2 lo (residual)
__device__ __forceinline__ void split2(float x, float y, uint32_t& hi, uint32_t& lo) {
    __nv_bfloat162 h = __floats2bfloat162_rn(x, y);
    __nv_bfloat162 l = __floats2bfloat162_rn(x - __low2float(h), y - __high2float(h));
    hi = *reinterpret_cast<uint32_t*>(&h);
    lo = *reinterpret_cast<uint32_t*>(&l);
}

// ---------------------------------------------------------------------------
// Embedding * sqrt(D) + sinusoidal PE (+ hi/lo split)
// ---------------------------------------------------------------------------
__global__ void embed_kernel(const int* __restrict__ src, const float* __restrict__ emb,
                             float* __restrict__ X, __nv_bfloat16* __restrict__ Xh,
                             __nv_bfloat16* __restrict__ Xl)
{
    int row = blockIdx.x;
    int s   = row % Sq;
    int tok = src[row];
    const float* er = emb + (size_t)tok * Dm;
    size_t base = (size_t)row * Dm;
    #pragma unroll
    for (int e = 0; e < 4; e++) {
        int d  = threadIdx.x + e * 256;
        int j2 = (d >> 1) * 2;
        float div = powf(10000.0f, (float)j2 / (float)Dm);
        float ang = (float)s / div;
        float pe  = (d & 1) ? cosf(ang) : sinf(ang);
        float v = er[d] * 32.0f + pe;
        X[base + d] = v;
        __nv_bfloat16 h = __float2bfloat16(v);
        Xh[base + d] = h;
        Xl[base + d] = __float2bfloat16(v - __bfloat162float(h));
    }
}

// ---------------------------------------------------------------------------
// Weight transpose + hi/lo split, batched over layers via blockIdx.z
// W[K,N] fp32 -> Thi/Tlo[N,K] bf16
// ---------------------------------------------------------------------------
__global__ __launch_bounds__(256)
void wt_convz_kernel(const float* __restrict__ W, __nv_bfloat16* __restrict__ Thi,
                     __nv_bfloat16* __restrict__ Tlo, int K, int N,
                     size_t src_stride, size_t dst_stride)
{
    int l = blockIdx.z;
    W   += (size_t)l * src_stride;
    Thi += (size_t)l * dst_stride;
    Tlo += (size_t)l * dst_stride;
    __shared__ float t[32][33];
    int n0 = blockIdx.x * 32, k0 = blockIdx.y * 32;
    int tx = threadIdx.x & 31, ty = threadIdx.x >> 5;
    #pragma unroll
    for (int j = 0; j < 4; j++)
        t[ty + j*8][tx] = W[(size_t)(k0 + ty + j*8) * N + n0 + tx];
    __syncthreads();
    #pragma unroll
    for (int j = 0; j < 4; j++) {
        float v = t[tx][ty + j*8];
        __nv_bfloat16 h = __float2bfloat16(v);
        __nv_bfloat16 lo = __float2bfloat16(v - __bfloat162float(h));
        size_t idx = (size_t)(n0 + ty + j*8) * K + k0 + tx;
        Thi[idx] = h; Tlo[idx] = lo;
    }
}

__global__ void pack_bias_kernel(const float* __restrict__ bq, const float* __restrict__ bk,
                                 const float* __restrict__ bv, float* __restrict__ dst)
{
    int idx = blockIdx.x * 256 + threadIdx.x;   // NL*3072 total
    int l = idx / (3*Dm), j = idx % (3*Dm);
    float v = (j < Dm) ? bq[l*Dm + j] : (j < 2*Dm) ? bk[l*Dm + j - Dm] : bv[l*Dm + j - 2*Dm];
    dst[idx] = v;
}

// ---------------------------------------------------------------------------
// HMMA bf16-split GEMM: C = A @ W + bias (+ReLU); optional fp32 and/or hi/lo out
// ---------------------------------------------------------------------------
#define TILEB  16384
#define STAGEB (4*TILEB)
#define NSTAGE 3
#define GEMM_SMEM (NSTAGE*STAGEB)

__device__ __forceinline__ void load_stage(
    uint32_t stage_base, const __nv_bfloat16* Ahi, const __nv_bfloat16* Alo,
    const __nv_bfloat16* Bhi, const __nv_bfloat16* Blo,
    int bm, int bn, int K, int k0, int tid)
{
    const __nv_bfloat16* srcs[4] = {Ahi, Alo, Bhi, Blo};
    #pragma unroll
    for (int tI = 0; tI < 4; tI++) {
        int rbase = (tI < 2) ? bm : bn;
        const __nv_bfloat16* src = srcs[tI];
        uint32_t tile = stage_base + tI * TILEB;
        #pragma unroll
        for (int i = 0; i < 4; i++) {
            int c   = tid + i * 256;
            int row = c >> 3, cb = c & 7;
            uint32_t dst = tile + row * 128 + ((cb ^ (row & 7)) << 4);
            const void* gp = src + ((size_t)(rbase + row) * K + k0 + cb * 8);
            asm volatile("cp.async.cg.shared.global [%0], [%1], 16;" :: "r"(dst), "l"(gp));
        }
    }
    asm volatile("cp.async.commit_group;" ::: "memory");
}

__global__ __launch_bounds__(256, 1)
void gemm_tc_kernel(const __nv_bfloat16* __restrict__ Ahi, const __nv_bfloat16* __restrict__ Alo,
                    const __nv_bfloat16* __restrict__ Bhi, const __nv_bfloat16* __restrict__ Blo,
                    const float* __restrict__ bias, float* __restrict__ Cf,
                    __nv_bfloat16* __restrict__ Chi, __nv_bfloat16* __restrict__ Clo,
                    int M, int N, int K, int relu)
{
    extern __shared__ __align__(1024) char smem[];
    uint32_t sb  = smem_u32(smem);
    int tid = threadIdx.x, wid = tid >> 5, lane = tid & 31;
    int bn = blockIdx.x * 128, bm = blockIdx.y * 128;
    int KSTEPS = K >> 6;

    int r0 = (wid & 1) * 64;
    int n0 = (wid >> 1) * 32;

    float acc[4][4][4];
    #pragma unroll
    for (int a = 0; a < 4; a++)
        #pragma unroll
        for (int b = 0; b < 4; b++)
            #pragma unroll
            for (int c = 0; c < 4; c++) acc[a][b][c] = 0.f;

    load_stage(sb,          Ahi, Alo, Bhi, Blo, bm, bn, K, 0,  tid);
    load_stage(sb + STAGEB, Ahi, Alo, Bhi, Blo, bm, bn, K, 64, tid);

    int a_ri = ((lane >> 3) & 1) * 8 + (lane & 7);
    int a_ci = (lane >> 4);
    int b_ri = ((lane >> 4) << 3) + (lane & 7);
    int b_ci = ((lane >> 3) & 1);

    for (int it = 0; it < KSTEPS; it++) {
        if (it == KSTEPS - 1) asm volatile("cp.async.wait_group 0;" ::: "memory");
        else                  asm volatile("cp.async.wait_group 1;" ::: "memory");
        __syncthreads();

        int nx = it + 2;
        if (nx < KSTEPS)
            load_stage(sb + (nx % NSTAGE) * STAGEB, Ahi, Alo, Bhi, Blo,
                       bm, bn, K, nx * 64, tid);

        uint32_t st  = sb + (it % NSTAGE) * STAGEB;
        uint32_t aHb = st, aLb = st + TILEB, bHb = st + 2*TILEB, bLb = st + 3*TILEB;

        #pragma unroll
        for (int ks = 0; ks < 4; ks++) {
            uint32_t aH[4][4], aL[4][4], bH[4][2], bL[4][2];
            int achk = 2 * ks + a_ci;
            #pragma unroll
            for (int mf = 0; mf < 4; mf++) {
                int row = r0 + mf * 16 + a_ri;
                uint32_t off = row * 128 + ((achk ^ (row & 7)) << 4);
                ldsm4(aH[mf], aHb + off);
                ldsm4(aL[mf], aLb + off);
            }
            int bchk = 2 * ks + b_ci;
            #pragma unroll
            for (int g = 0; g < 2; g++) {
                int row = n0 + g * 16 + b_ri;
                uint32_t off = row * 128 + ((bchk ^ (row & 7)) << 4);
                uint32_t t[4];
                ldsm4(t, bHb + off);
                bH[2*g][0] = t[0]; bH[2*g][1] = t[1];
                bH[2*g+1][0] = t[2]; bH[2*g+1][1] = t[3];
                ldsm4(t, bLb + off);
                bL[2*g][0] = t[0]; bL[2*g][1] = t[1];
                bL[2*g+1][0] = t[2]; bL[2*g+1][1] = t[3];
            }
            #pragma unroll
            for (int mf = 0; mf < 4; mf++)
                #pragma unroll
                for (int nf = 0; nf < 4; nf++) {
                    mma16816(acc[mf][nf], aH[mf], bH[nf]);
                    mma16816(acc[mf][nf], aL[mf], bH[nf]);
                    mma16816(acc[mf][nf], aH[mf], bL[nf]);
                }
        }
    }

    int lrow = lane >> 2, lcol = (lane & 3) * 2;
    #pragma unroll
    for (int mf = 0; mf < 4; mf++) {
        int row = bm + r0 + mf * 16 + lrow;
        #pragma unroll
        for (int nf = 0; nf < 4; nf++) {
            int col = bn + n0 + nf * 8 + lcol;
            float b0 = bias[col], b1 = bias[col + 1];
            float2 v0, v1;
            v0.x = acc[mf][nf][0] + b0; v0.y = acc[mf][nf][1] + b1;
            v1.x = acc[mf][nf][2] + b0; v1.y = acc[mf][nf][3] + b1;
            if (relu) {
                v0.x = fmaxf(v0.x, 0.f); v0.y = fmaxf(v0.y, 0.f);
                v1.x = fmaxf(v1.x, 0.f); v1.y = fmaxf(v1.y, 0.f);
            }
            if (Cf) {
                *(float2*)(Cf + (size_t)row * N + col)       = v0;
                *(float2*)(Cf + (size_t)(row + 8) * N + col) = v1;
            }
            if (Chi) {
                uint32_t h0, l0u, h1, l1u;
                split2(v0.x, v0.y, h0, l0u);
                split2(v1.x, v1.y, h1, l1u);
                *(uint32_t*)(Chi + (size_t)row * N + col)       = h0;
                *(uint32_t*)(Clo + (size_t)row * N + col)       = l0u;
                *(uint32_t*)(Chi + (size_t)(row + 8) * N + col) = h1;
                *(uint32_t*)(Clo + (size_t)(row + 8) * N + col) = l1u;
            }
        }
    }
}

// ---------------------------------------------------------------------------
// Tensor-core flash attention (bf16 hi/lo split, fp32 accum)
// block = (128 q rows, head, batch); 8 warps x 16 q rows each
// ---------------------------------------------------------------------------
#define A_QH 0
#define A_QL 16384
#define A_ST 32768          /* stage s at A_ST + s*65536: KH, KL, VH, VL (16KB each) */
#define A_MSK 163840
#define ATTN_SMEM (163840 + 4096)

__device__ __forceinline__ void attn_load_tile(uint32_t dst, const __nv_bfloat16* src,
                                               size_t row0, int colbase, int tid)
{
    #pragma unroll
    for (int i = 0; i < 4; i++) {
        int c = tid + i * 256;
        int row = c >> 3, cb = c & 7;
        uint32_t d = dst + row * 128 + ((cb ^ (row & 7)) << 4);
        const void* gp = src + (row0 + row) * (size_t)(3 * Dm) + colbase + cb * 8;
        asm volatile("cp.async.cg.shared.global [%0], [%1], 16;" :: "r"(d), "l"(gp));
    }
}

__global__ __launch_bounds__(256, 1)
void attn_tc_kernel(const __nv_bfloat16* __restrict__ QKVh, const __nv_bfloat16* __restrict__ QKVl,
                    const int* __restrict__ mask, __nv_bfloat16* __restrict__ Oh,
                    __nv_bfloat16* __restrict__ Ol)
{
    extern __shared__ __align__(1024) char smem[];
    uint32_t sb = smem_u32(smem);
    int tid = threadIdx.x, wid = tid >> 5, lane = tid & 31;
    int q0 = blockIdx.x * 128, h = blockIdx.y, b = blockIdx.z;

    int* msm = (int*)(smem + A_MSK);
    #pragma unroll
    for (int i = 0; i < 4; i++) msm[tid + i * 256] = mask[b * Sq + tid + i * 256];

    size_t rowQ = (size_t)b * Sq + q0;
    attn_load_tile(sb + A_QH, QKVh, rowQ, h * HDim, tid);
    attn_load_tile(sb + A_QL, QKVl, rowQ, h * HDim, tid);
    asm volatile("cp.async.commit_group;" ::: "memory");
    size_t rowK = (size_t)b * Sq;
    attn_load_tile(sb + A_ST,         QKVh, rowK, Dm + h * HDim, tid);
    attn_load_tile(sb + A_ST + 16384, QKVl, rowK, Dm + h * HDim, tid);
    attn_load_tile(sb + A_ST + 32768, QKVh, rowK, 2 * Dm + h * HDim, tid);
    attn_load_tile(sb + A_ST + 49152, QKVl, rowK, 2 * Dm + h * HDim, tid);
    asm volatile("cp.async.commit_group;" ::: "memory");

    float m0 = -1e30f, m1 = -1e30f, l0 = 0.f, l1 = 0.f;
    float acc[8][4];
    #pragma unroll
    for (int o = 0; o < 8; o++)
        #pragma unroll
        for (int e = 0; e < 4; e++) acc[o][e] = 0.f;

    int a_ri = ((lane >> 3) & 1) * 8 + (lane & 7);
    int a_ci = (lane >> 4);
    int b_ri = ((lane >> 4) << 3) + (lane & 7);
    int b_ci = ((lane >> 3) & 1);

    for (int c = 0; c < 8; c++) {
        if (c < 7) {
            uint32_t stg = sb + A_ST + ((c + 1) & 1) * 65536;
            size_t rk = (size_t)b * Sq + (c + 1) * 128;
            attn_load_tile(stg,         QKVh, rk, Dm + h * HDim, tid);
            attn_load_tile(stg + 16384, QKVl, rk, Dm + h * HDim, tid);
            attn_load_tile(stg + 32768, QKVh, rk, 2 * Dm + h * HDim, tid);
            attn_load_tile(stg + 49152, QKVl, rk, 2 * Dm + h * HDim, tid);
            asm volatile("cp.async.commit_group;" ::: "memory");
            asm volatile("cp.async.wait_group 1;" ::: "memory");
        } else {
            asm volatile("cp.async.wait_group 0;" ::: "memory");
        }
        __syncthreads();

        uint32_t stg = sb + A_ST + (c & 1) * 65536;
        uint32_t KH = stg, KL = stg + 16384, VH = stg + 32768, VL = stg + 49152;

        // ---- S = Q K^T (3-term split) ----
        float s[16][4];
        #pragma unroll
        for (int nf = 0; nf < 16; nf++)
            #pragma unroll
            for (int e = 0; e < 4; e++) s[nf][e] = 0.f;

        #pragma unroll
        for (int ks = 0; ks < 4; ks++) {
            uint32_t aH[4], aL[4];
            int qrow = wid * 16 + a_ri;
            uint32_t aoff = qrow * 128 + (((ks * 2 + a_ci) ^ (qrow & 7)) << 4);
            ldsm4(aH, sb + A_QH + aoff);
            ldsm4(aL, sb + A_QL + aoff);
            #pragma unroll
            for (int g = 0; g < 8; g++) {
                int krow = g * 16 + b_ri;
                uint32_t boff = krow * 128 + (((ks * 2 + b_ci) ^ (krow & 7)) << 4);
                uint32_t tH[4], tL[4];
                ldsm4(tH, KH + boff);
                ldsm4(tL, KL + boff);
                mma16816(s[2*g],   aH, tH);
                mma16816(s[2*g],   aL, tH);
                mma16816(s[2*g],   aH, tL);
                mma16816(s[2*g+1], aH, tH + 2);
                mma16816(s[2*g+1], aL, tH + 2);
                mma16816(s[2*g+1], aH, tL + 2);
            }
        }

        // ---- scale + mask ----
        int k0c = c * 128;
        #pragma unroll
        for (int nf = 0; nf < 16; nf++) {
            int col = k0c + nf * 8 + (lane & 3) * 2;
            float ad0 = (msm[col]     == 0) ? -1e10f : 0.f;
            float ad1 = (msm[col + 1] == 0) ? -1e10f : 0.f;
            s[nf][0] = s[nf][0] * 0.125f + ad0;
            s[nf][1] = s[nf][1] * 0.125f + ad1;
            s[nf][2] = s[nf][2] * 0.125f + ad0;
            s[nf][3] = s[nf][3] * 0.125f + ad1;
        }

        // ---- online softmax ----
        float tm0 = -1e30f, tm1 = -1e30f;
        #pragma unroll
        for (int nf = 0; nf < 16; nf++) {
            tm0 = fmaxf(tm0, fmaxf(s[nf][0], s[nf][1]));
            tm1 = fmaxf(tm1, fmaxf(s[nf][2], s[nf][3]));
        }
        tm0 = fmaxf(tm0, __shfl_xor_sync(0xffffffffu, tm0, 1));
        tm0 = fmaxf(tm0, __shfl_xor_sync(0xffffffffu, tm0, 2));
        tm1 = fmaxf(tm1, __shfl_xor_sync(0xffffffffu, tm1, 1));
        tm1 = fmaxf(tm1, __shfl_xor_sync(0xffffffffu, tm1, 2));
        float nm0 = fmaxf(m0, tm0), nm1 = fmaxf(m1, tm1);
        float cr0 = __expf(m0 - nm0), cr1 = __expf(m1 - nm1);
        float rs0 = 0.f, rs1 = 0.f;
        #pragma unroll
        for (int nf = 0; nf < 16; nf++) {
            s[nf][0] = __expf(s[nf][0] - nm0); rs0 += s[nf][0];
            s[nf][1] = __expf(s[nf][1] - nm0); rs0 += s[nf][1];
            s[nf][2] = __expf(s[nf][2] - nm1); rs1 += s[nf][2];
            s[nf][3] = __expf(s[nf][3] - nm1); rs1 += s[nf][3];
        }
        rs0 += __shfl_xor_sync(0xffffffffu, rs0, 1);
        rs0 += __shfl_xor_sync(0xffffffffu, rs0, 2);
        rs1 += __shfl_xor_sync(0xffffffffu, rs1, 1);
        rs1 += __shfl_xor_sync(0xffffffffu, rs1, 2);
        l0 = l0 * cr0 + rs0;  l1 = l1 * cr1 + rs1;
        m0 = nm0;  m1 = nm1;
        #pragma unroll
        for (int o = 0; o < 8; o++) {
            acc[o][0] *= cr0; acc[o][1] *= cr0;
            acc[o][2] *= cr1; acc[o][3] *= cr1;
        }

        // ---- O += P V (3-term split; P from registers) ----
        #pragma unroll
        for (int kp = 0; kp < 8; kp++) {
            uint32_t pH[4], pL[4];
            split2(s[2*kp][0],   s[2*kp][1],   pH[0], pL[0]);
            split2(s[2*kp][2],   s[2*kp][3],   pH[1], pL[1]);
            split2(s[2*kp+1][0], s[2*kp+1][1], pH[2], pL[2]);
            split2(s[2*kp+1][2], s[2*kp+1][3], pH[3], pL[3]);
            int vrow = kp * 16 + (lane & 7) + ((lane >> 3) & 1) * 8;
            int vck  = (lane >> 4);
            #pragma unroll
            for (int vg = 0; vg < 4; vg++) {
                uint32_t off = vrow * 128 + (((vg * 2 + vck) ^ (vrow & 7)) << 4);
                uint32_t tH[4], tL[4];
                ldsm4t(tH, VH + off);
                ldsm4t(tL, VL + off);
                mma16816(acc[2*vg],   pH, tH);
                mma16816(acc[2*vg],   pL, tH);
                mma16816(acc[2*vg],   pH, tL);
                mma16816(acc[2*vg+1], pH, tH + 2);
                mma16816(acc[2*vg+1], pL, tH + 2);
                mma16816(acc[2*vg+1], pH, tL + 2);
            }
        }
        __syncthreads();
    }

    // ---- normalize + write O (hi/lo bf16) ----
    float i0 = 1.f / l0, i1 = 1.f / l1;
    size_t base0 = ((size_t)b * Sq + q0 + wid * 16 + (lane >> 2)) * Dm + h * HDim + (lane & 3) * 2;
    size_t base1 = base0 + (size_t)8 * Dm;
    #pragma unroll
    for (int nf = 0; nf < 8; nf++) {
        uint32_t h0, l0u, h1, l1u;
        split2(acc[nf][0] * i0, acc[nf][1] * i0, h0, l0u);
        split2(acc[nf][2] * i1, acc[nf][3] * i1, h1, l1u);
        *(uint32_t*)(Oh + base0 + nf * 8) = h0;
        *(uint32_t*)(Ol + base0 + nf * 8) = l0u;
        *(uint32_t*)(Oh + base1 + nf * 8) = h1;
        *(uint32_t*)(Ol + base1 + nf * 8) = l1u;
    }
}

// ---------------------------------------------------------------------------
// dst = LayerNorm(x + t) * g + b  (+ optional hi/lo split outputs)
// ---------------------------------------------------------------------------
__device__ __forceinline__ float block_reduce_sum(float v, float* red)
{
    #pragma unroll
    for (int o = 16; o > 0; o >>= 1) v += __shfl_xor_sync(0xffffffffu, v, o);
    int w = threadIdx.x >> 5;
    if ((threadIdx.x & 31) == 0) red[w] = v;
    __syncthreads();
    if (threadIdx.x < 32) {
        float r = (threadIdx.x < 8) ? red[threadIdx.x] : 0.f;
        #pragma unroll
        for (int o = 4; o > 0; o >>= 1) r += __shfl_xor_sync(0xffffffffu, r, o);
        if (threadIdx.x == 0) red[0] = r;
    }
    __syncthreads();
    float r = red[0];
    __syncthreads();
    return r;
}

__global__ __launch_bounds__(256)
void add_ln_kernel(const float* __restrict__ x, const float* __restrict__ t,
                   const float* __restrict__ g, const float* __restrict__ bt,
                   float* __restrict__ dst, __nv_bfloat16* __restrict__ dhi,
                   __nv_bfloat16* __restrict__ dlo)
{
    __shared__ float red[8];
    size_t base = (size_t)blockIdx.x * Dm;
    float v[4]; float s = 0.f;
    #pragma unroll
    for (int e = 0; e < 4; e++) {
        int c = threadIdx.x + e * 256;
        v[e] = x[base + c] + t[base + c];
        s += v[e];
    }
    s = block_reduce_sum(s, red);
    float mu = s * (1.0f / Dm);
    float q = 0.f;
    #pragma unroll
    for (int e = 0; e < 4; e++) { float d = v[e] - mu; q += d * d; }
    q = block_reduce_sum(q, red);
    float inv = rsqrtf(q * (1.0f / Dm) + 1e-5f);
    #pragma unroll
    for (int e = 0; e < 4; e++) {
        int c = threadIdx.x + e * 256;
        float o = (v[e] - mu) * inv * g[c] + bt[c];
        dst[base + c] = o;
        if (dhi) {
            __nv_bfloat16 h = __float2bfloat16(o);
            dhi[base + c] = h;
            dlo[base + c] = __float2bfloat16(o - __bfloat162float(h));
        }
    }
}

// ---------------------------------------------------------------------------
extern "C" void kernel_launch(void* const* d_in, const int* in_sizes, int n_in,
                              void* d_out, int out_size)
{
    const int*   src = (const int*)d_in[0];
    const int*   msk = (const int*)d_in[1];
    const float* emb = (const float*)d_in[2];
    const float* Wq  = (const float*)d_in[3];
    const float* bq  = (const float*)d_in[4];
    const float* Wk  = (const float*)d_in[5];
    const float* bk  = (const float*)d_in[6];
    const float* Wv  = (const float*)d_in[7];
    const float* bv  = (const float*)d_in[8];
    const float* Wo  = (const float*)d_in[9];
    const float* bo  = (const float*)d_in[10];
    const float* g1  = (const float*)d_in[11];
    const float* b1n = (const float*)d_in[12];
    const float* W1  = (const float*)d_in[13];
    const float* b1  = (const float*)d_in[14];
    const float* W2  = (const float*)d_in[15];
    const float* b2  = (const float*)d_in[16];
    const float* g2  = (const float*)d_in[17];
    const float* b2n = (const float*)d_in[18];
    float* out = (float*)d_out;

    float* f32 = nullptr;
    cudaGetSymbolAddress((void**)&f32, g_f32);
    float* X  = f32;
    float* T2 = f32 + (size_t)NTOK * Dm;

    __nv_bfloat16 *Xh, *Xl, *Qh, *Ql, *Ohb, *Olb, *Hh, *Hl, *Wh, *Wl;
    float* bqkv;
    cudaGetSymbolAddress((void**)&Xh,  g_xh);
    cudaGetSymbolAddress((void**)&Xl,  g_xl);
    cudaGetSymbolAddress((void**)&Qh,  g_qkvh);
    cudaGetSymbolAddress((void**)&Ql,  g_qkvl);
    cudaGetSymbolAddress((void**)&Ohb, g_oh);
    cudaGetSymbolAddress((void**)&Olb, g_ol);
    cudaGetSymbolAddress((void**)&Hh,  g_hh);
    cudaGetSymbolAddress((void**)&Hl,  g_hl);
    cudaGetSymbolAddress((void**)&Wh,  g_wt_hi);
    cudaGetSymbolAddress((void**)&Wl,  g_wt_lo);
    cudaGetSymbolAddress((void**)&bqkv, g_bqkv);

    cudaFuncSetAttribute((const void*)gemm_tc_kernel,
                         cudaFuncAttributeMaxDynamicSharedMemorySize, GEMM_SMEM);
    cudaFuncSetAttribute((const void*)attn_tc_kernel,
                         cudaFuncAttributeMaxDynamicSharedMemorySize, ATTN_SMEM);

    const size_t M1  = (size_t)1024 * 1024;
    const size_t LWT = 12 * M1;

    // weights: transpose + split, batched over layers
    wt_convz_kernel<<<dim3(32, 32, NL), 256>>>(Wq, Wh,          Wl,          Dm, Dm, (size_t)Dm*Dm, LWT);
    wt_convz_kernel<<<dim3(32, 32, NL), 256>>>(Wk, Wh + M1,     Wl + M1,     Dm, Dm, (size_t)Dm*Dm, LWT);
    wt_convz_kernel<<<dim3(32, 32, NL), 256>>>(Wv, Wh + 2*M1,   Wl + 2*M1,   Dm, Dm, (size_t)Dm*Dm, LWT);
    wt_convz_kernel<<<dim3(32, 32, NL), 256>>>(Wo, Wh + 3*M1,   Wl + 3*M1,   Dm, Dm, (size_t)Dm*Dm, LWT);
    wt_convz_kernel<<<dim3(Ff/32, Dm/32, NL), 256>>>(W1, Wh + 4*M1, Wl + 4*M1, Dm, Ff, (size_t)Dm*Ff, LWT);
    wt_convz_kernel<<<dim3(Dm/32, Ff/32, NL), 256>>>(W2, Wh + 8*M1, Wl + 8*M1, Ff, Dm, (size_t)Dm*Ff, LWT);
    pack_bias_kernel<<<NL * 3 * Dm / 256, 256>>>(bq, bk, bv, bqkv);

    embed_kernel<<<NTOK, 256>>>(src, emb, X, Xh, Xl);

    dim3 gQKV(3 * Dm / 128, NTOK / 128);  // (24, 64)
    dim3 gD(Dm / 128, NTOK / 128);        // (8, 64)
    dim3 gF(Ff / 128, NTOK / 128);        // (32, 64)
    dim3 gA(Sq / 128, Hn, Bz);            // (8, 16, 8)

    for (int l = 0; l < NL; l++) {
        size_t oD = (size_t)l * Dm, oF = (size_t)l * Ff;
        size_t wb = (size_t)l * LWT;
        bool last = (l == NL - 1);

        gemm_tc_kernel<<<gQKV, 256, GEMM_SMEM>>>(Xh, Xl, Wh + wb, Wl + wb,
            bqkv + (size_t)l * 3 * Dm, nullptr, Qh, Ql, NTOK, 3 * Dm, Dm, 0);
        attn_tc_kernel<<<gA, 256, ATTN_SMEM>>>(Qh, Ql, msk, Ohb, Olb);
        gemm_tc_kernel<<<gD, 256, GEMM_SMEM>>>(Ohb, Olb, Wh + wb + 3*M1, Wl + wb + 3*M1,
            bo + oD, T2, nullptr, nullptr, NTOK, Dm, Dm, 0);
        add_ln_kernel<<<NTOK, 256>>>(X, T2, g1 + oD, b1n + oD, X, Xh, Xl);
        gemm_tc_kernel<<<gF, 256, GEMM_SMEM>>>(Xh, Xl, Wh + wb + 4*M1, Wl + wb + 4*M1,
            b1 + oF, nullptr, Hh, Hl, NTOK, Ff, Dm, 1);
        gemm_tc_kernel<<<gD, 256, GEMM_SMEM>>>(Hh, Hl, Wh + wb + 8*M1, Wl + wb + 8*M1,
            b2 + oD, T2, nullptr, nullptr, NTOK, Dm, Ff, 0);
        add_ln_kernel<<<NTOK, 256>>>(X, T2, g2 + oD, b2n + oD,
            last ? out : X, last ? nullptr : Xh, Xl);
    }
}